// round 1
// baseline (speedup 1.0000x reference)
#include <cuda_runtime.h>

// SpikingMLP: s2 = LIF(LIF(x@W1^T + b1) @ W2^T + b2)
// x: (T=4, B=32, N=196, D=768)  -> M = B*N = 6272 rows per t
// W1: (3072, 768), W2: (768, 3072), biases zero-shaped but applied anyway.
//
// Two fused kernels:
//   K1: s1[t,m,h] = LIF_t( x[t,m,:] @ W1[h,:] + b1[h] )   -> scratch (fp32, binary values)
//   K2: s2[t,m,d] = LIF_t( s1[t,m,:] @ W2[d,:] + b2[d] )  -> d_out
//
// Each block owns a 64x64 (m,n) tile for ALL 4 timesteps so the LIF scan over t
// happens in registers in the epilogue. Strict fp32 FFMA everywhere (binary-spike
// output is flip-sensitive; tensor-core precision deferred until margin measured).

#define T_STEPS 4
#define M_ROWS  6272        // 32*196
#define H_DIM   3072
#define D_DIM   768

// scratch for binary spikes s1 (stored fp32 for GEMM2 symmetry): 4*6272*3072 floats = ~308MB
__device__ float g_s1[(size_t)T_STEPS * M_ROWS * H_DIM];

// Tiled fp32 GEMM (A row-major [T][M][K], W row-major [N][K]) + fused LIF over T.
// BM=BN=64, BK=16, 256 threads, 4x4 microtile per thread per t (64 accumulators).
__global__ __launch_bounds__(256, 2)
void gemm_lif_kernel(const float* __restrict__ A,
                     const float* __restrict__ W,
                     const float* __restrict__ bias,
                     float* __restrict__ out,
                     int M, int N, int K)
{
    constexpr int BK = 16;
    __shared__ float As[T_STEPS][BK][64];
    __shared__ float Bs[BK][64];

    const int tid = threadIdx.x;
    const int tx  = tid & 15;        // n-direction (0..15), 4 cols each
    const int ty  = tid >> 4;        // m-direction (0..15), 4 rows each
    const int m0  = blockIdx.y * 64;
    const int n0  = blockIdx.x * 64;

    // loader mapping: 4 consecutive threads cover 16 contiguous K floats of one row
    const int lr = tid >> 2;         // 0..63 : row within tile
    const int lc = (tid & 3) * 4;    // 0,4,8,12 : col group within BK

    float acc[T_STEPS][4][4];
#pragma unroll
    for (int t = 0; t < T_STEPS; t++)
#pragma unroll
        for (int i = 0; i < 4; i++)
#pragma unroll
            for (int j = 0; j < 4; j++)
                acc[t][i][j] = 0.0f;

    const float* Arow0 = A + (size_t)(m0 + lr) * K + lc;
    const float* Wrow  = W + (size_t)(n0 + lr) * K + lc;
    const size_t planeA = (size_t)M * K;

    for (int k0 = 0; k0 < K; k0 += BK) {
        // load A tiles for all 4 timesteps (transpose into [k][m] layout)
#pragma unroll
        for (int t = 0; t < T_STEPS; t++) {
            float4 v = *(const float4*)(Arow0 + (size_t)t * planeA + k0);
            As[t][lc + 0][lr] = v.x;
            As[t][lc + 1][lr] = v.y;
            As[t][lc + 2][lr] = v.z;
            As[t][lc + 3][lr] = v.w;
        }
        // load W tile
        {
            float4 v = *(const float4*)(Wrow + k0);
            Bs[lc + 0][lr] = v.x;
            Bs[lc + 1][lr] = v.y;
            Bs[lc + 2][lr] = v.z;
            Bs[lc + 3][lr] = v.w;
        }
        __syncthreads();

#pragma unroll
        for (int kk = 0; kk < BK; kk++) {
            const float4 b4 = *(const float4*)&Bs[kk][tx * 4];
#pragma unroll
            for (int t = 0; t < T_STEPS; t++) {
                const float4 a4 = *(const float4*)&As[t][kk][ty * 4];
                acc[t][0][0] += a4.x * b4.x; acc[t][0][1] += a4.x * b4.y;
                acc[t][0][2] += a4.x * b4.z; acc[t][0][3] += a4.x * b4.w;
                acc[t][1][0] += a4.y * b4.x; acc[t][1][1] += a4.y * b4.y;
                acc[t][1][2] += a4.y * b4.z; acc[t][1][3] += a4.y * b4.w;
                acc[t][2][0] += a4.z * b4.x; acc[t][2][1] += a4.z * b4.y;
                acc[t][2][2] += a4.z * b4.z; acc[t][2][3] += a4.z * b4.w;
                acc[t][3][0] += a4.w * b4.x; acc[t][3][1] += a4.w * b4.y;
                acc[t][3][2] += a4.w * b4.z; acc[t][3][3] += a4.w * b4.w;
            }
        }
        __syncthreads();
    }

    // ---- Epilogue: bias + LIF scan over T, write binary spikes ----
    const float4 bv = *(const float4*)(bias + n0 + tx * 4);
#pragma unroll
    for (int i = 0; i < 4; i++) {
        const size_t row = (size_t)(m0 + ty * 4 + i);
        float v0 = 0.f, v1 = 0.f, v2 = 0.f, v3 = 0.f;
#pragma unroll
        for (int t = 0; t < T_STEPS; t++) {
            // v <- v + (h - v)/tau  (tau=2, exact *0.5)
            float h0 = acc[t][i][0] + bv.x;
            float h1 = acc[t][i][1] + bv.y;
            float h2 = acc[t][i][2] + bv.z;
            float h3 = acc[t][i][3] + bv.w;
            v0 = v0 + (h0 - v0) * 0.5f;
            v1 = v1 + (h1 - v1) * 0.5f;
            v2 = v2 + (h2 - v2) * 0.5f;
            v3 = v3 + (h3 - v3) * 0.5f;
            float s0 = (v0 >= 1.0f) ? 1.0f : 0.0f;
            float s1 = (v1 >= 1.0f) ? 1.0f : 0.0f;
            float s2 = (v2 >= 1.0f) ? 1.0f : 0.0f;
            float s3 = (v3 >= 1.0f) ? 1.0f : 0.0f;
            float4 sv = make_float4(s0, s1, s2, s3);
            *(float4*)(out + ((size_t)t * M + row) * N + n0 + tx * 4) = sv;
            // hard reset, v_reset = 0:  v *= (1 - s)
            v0 *= (1.0f - s0);
            v1 *= (1.0f - s1);
            v2 *= (1.0f - s2);
            v3 *= (1.0f - s3);
        }
    }
}

extern "C" void kernel_launch(void* const* d_in, const int* in_sizes, int n_in,
                              void* d_out, int out_size)
{
    const float* x  = (const float*)d_in[0];   // (4,32,196,768)
    const float* W1 = (const float*)d_in[1];   // (3072,768)
    const float* b1 = (const float*)d_in[2];   // (3072,)
    const float* W2 = (const float*)d_in[3];   // (768,3072)
    const float* b2 = (const float*)d_in[4];   // (768,)
    float* out = (float*)d_out;                // (4,32,196,768)

    float* s1_ptr = nullptr;
    cudaGetSymbolAddress((void**)&s1_ptr, g_s1);

    // K1: x @ W1^T + b1 -> LIF -> s1     (M=6272, N=3072, K=768)
    {
        dim3 grid(H_DIM / 64, M_ROWS / 64);   // (48, 98)
        gemm_lif_kernel<<<grid, 256>>>(x, W1, b1, s1_ptr, M_ROWS, H_DIM, D_DIM);
    }
    // K2: s1 @ W2^T + b2 -> LIF -> out   (M=6272, N=768, K=3072)
    {
        dim3 grid(D_DIM / 64, M_ROWS / 64);   // (12, 98)
        gemm_lif_kernel<<<grid, 256>>>(s1_ptr, W2, b2, out, M_ROWS, D_DIM, H_DIM);
    }
}

// round 2
// speedup vs baseline: 1.0005x; 1.0005x over previous
#include <cuda_runtime.h>

// SpikingMLP: s2 = LIF(LIF(x@W1^T + b1) @ W2^T + b2)
// x: (T=4, B=32, N=196, D=768)  -> M = B*N = 6272 rows per t
// W1: (3072, 768), W2: (768, 3072), biases zero-shaped but applied anyway.
//
// Two fused kernels:
//   K1: s1[t,m,h] = LIF_t( x[t,m,:] @ W1[h,:] + b1[h] )   -> scratch (fp32, binary values)
//   K2: s2[t,m,d] = LIF_t( s1[t,m,:] @ W2[d,:] + b2[d] )  -> d_out
//
// Each block owns a 64x64 (m,n) tile for ALL 4 timesteps so the LIF scan over t
// happens in registers in the epilogue. Strict fp32 FFMA everywhere (binary-spike
// output is flip-sensitive; tensor-core precision deferred until margin measured).

#define T_STEPS 4
#define M_ROWS  6272        // 32*196
#define H_DIM   3072
#define D_DIM   768

// scratch for binary spikes s1 (stored fp32 for GEMM2 symmetry): 4*6272*3072 floats = ~308MB
__device__ float g_s1[(size_t)T_STEPS * M_ROWS * H_DIM];

// Tiled fp32 GEMM (A row-major [T][M][K], W row-major [N][K]) + fused LIF over T.
// BM=BN=64, BK=16, 256 threads, 4x4 microtile per thread per t (64 accumulators).
__global__ __launch_bounds__(256, 2)
void gemm_lif_kernel(const float* __restrict__ A,
                     const float* __restrict__ W,
                     const float* __restrict__ bias,
                     float* __restrict__ out,
                     int M, int N, int K)
{
    constexpr int BK = 16;
    __shared__ float As[T_STEPS][BK][64];
    __shared__ float Bs[BK][64];

    const int tid = threadIdx.x;
    const int tx  = tid & 15;        // n-direction (0..15), 4 cols each
    const int ty  = tid >> 4;        // m-direction (0..15), 4 rows each
    const int m0  = blockIdx.y * 64;
    const int n0  = blockIdx.x * 64;

    // loader mapping: 4 consecutive threads cover 16 contiguous K floats of one row
    const int lr = tid >> 2;         // 0..63 : row within tile
    const int lc = (tid & 3) * 4;    // 0,4,8,12 : col group within BK

    float acc[T_STEPS][4][4];
#pragma unroll
    for (int t = 0; t < T_STEPS; t++)
#pragma unroll
        for (int i = 0; i < 4; i++)
#pragma unroll
            for (int j = 0; j < 4; j++)
                acc[t][i][j] = 0.0f;

    const float* Arow0 = A + (size_t)(m0 + lr) * K + lc;
    const float* Wrow  = W + (size_t)(n0 + lr) * K + lc;
    const size_t planeA = (size_t)M * K;

    for (int k0 = 0; k0 < K; k0 += BK) {
        // load A tiles for all 4 timesteps (transpose into [k][m] layout)
#pragma unroll
        for (int t = 0; t < T_STEPS; t++) {
            float4 v = *(const float4*)(Arow0 + (size_t)t * planeA + k0);
            As[t][lc + 0][lr] = v.x;
            As[t][lc + 1][lr] = v.y;
            As[t][lc + 2][lr] = v.z;
            As[t][lc + 3][lr] = v.w;
        }
        // load W tile
        {
            float4 v = *(const float4*)(Wrow + k0);
            Bs[lc + 0][lr] = v.x;
            Bs[lc + 1][lr] = v.y;
            Bs[lc + 2][lr] = v.z;
            Bs[lc + 3][lr] = v.w;
        }
        __syncthreads();

#pragma unroll
        for (int kk = 0; kk < BK; kk++) {
            const float4 b4 = *(const float4*)&Bs[kk][tx * 4];
#pragma unroll
            for (int t = 0; t < T_STEPS; t++) {
                const float4 a4 = *(const float4*)&As[t][kk][ty * 4];
                acc[t][0][0] += a4.x * b4.x; acc[t][0][1] += a4.x * b4.y;
                acc[t][0][2] += a4.x * b4.z; acc[t][0][3] += a4.x * b4.w;
                acc[t][1][0] += a4.y * b4.x; acc[t][1][1] += a4.y * b4.y;
                acc[t][1][2] += a4.y * b4.z; acc[t][1][3] += a4.y * b4.w;
                acc[t][2][0] += a4.z * b4.x; acc[t][2][1] += a4.z * b4.y;
                acc[t][2][2] += a4.z * b4.z; acc[t][2][3] += a4.z * b4.w;
                acc[t][3][0] += a4.w * b4.x; acc[t][3][1] += a4.w * b4.y;
                acc[t][3][2] += a4.w * b4.z; acc[t][3][3] += a4.w * b4.w;
            }
        }
        __syncthreads();
    }

    // ---- Epilogue: bias + LIF scan over T, write binary spikes ----
    const float4 bv = *(const float4*)(bias + n0 + tx * 4);
#pragma unroll
    for (int i = 0; i < 4; i++) {
        const size_t row = (size_t)(m0 + ty * 4 + i);
        float v0 = 0.f, v1 = 0.f, v2 = 0.f, v3 = 0.f;
#pragma unroll
        for (int t = 0; t < T_STEPS; t++) {
            // v <- v + (h - v)/tau  (tau=2, exact *0.5)
            float h0 = acc[t][i][0] + bv.x;
            float h1 = acc[t][i][1] + bv.y;
            float h2 = acc[t][i][2] + bv.z;
            float h3 = acc[t][i][3] + bv.w;
            v0 = v0 + (h0 - v0) * 0.5f;
            v1 = v1 + (h1 - v1) * 0.5f;
            v2 = v2 + (h2 - v2) * 0.5f;
            v3 = v3 + (h3 - v3) * 0.5f;
            float s0 = (v0 >= 1.0f) ? 1.0f : 0.0f;
            float s1 = (v1 >= 1.0f) ? 1.0f : 0.0f;
            float s2 = (v2 >= 1.0f) ? 1.0f : 0.0f;
            float s3 = (v3 >= 1.0f) ? 1.0f : 0.0f;
            float4 sv = make_float4(s0, s1, s2, s3);
            *(float4*)(out + ((size_t)t * M + row) * N + n0 + tx * 4) = sv;
            // hard reset, v_reset = 0:  v *= (1 - s)
            v0 *= (1.0f - s0);
            v1 *= (1.0f - s1);
            v2 *= (1.0f - s2);
            v3 *= (1.0f - s3);
        }
    }
}

extern "C" void kernel_launch(void* const* d_in, const int* in_sizes, int n_in,
                              void* d_out, int out_size)
{
    const float* x  = (const float*)d_in[0];   // (4,32,196,768)
    const float* W1 = (const float*)d_in[1];   // (3072,768)
    const float* b1 = (const float*)d_in[2];   // (3072,)
    const float* W2 = (const float*)d_in[3];   // (768,3072)
    const float* b2 = (const float*)d_in[4];   // (768,)
    float* out = (float*)d_out;                // (4,32,196,768)

    float* s1_ptr = nullptr;
    cudaGetSymbolAddress((void**)&s1_ptr, g_s1);

    // K1: x @ W1^T + b1 -> LIF -> s1     (M=6272, N=3072, K=768)
    {
        dim3 grid(H_DIM / 64, M_ROWS / 64);   // (48, 98)
        gemm_lif_kernel<<<grid, 256>>>(x, W1, b1, s1_ptr, M_ROWS, H_DIM, D_DIM);
    }
    // K2: s1 @ W2^T + b2 -> LIF -> out   (M=6272, N=768, K=3072)
    {
        dim3 grid(D_DIM / 64, M_ROWS / 64);   // (12, 98)
        gemm_lif_kernel<<<grid, 256>>>(s1_ptr, W2, b2, out, M_ROWS, D_DIM, H_DIM);
    }
}

// round 5
// speedup vs baseline: 3.6112x; 3.6093x over previous
#include <cuda_runtime.h>
#include <cuda_fp16.h>
#include <cstdint>

// ============================================================================
// SpikingMLP via fp16 split-product HMMA (mma.sync, portable sm_100 path).
//   A1' = [xh | xm | xh]  (K=2304)   W1' = [w1h | w1h | w1m]
//   h   = A1' @ W1'^T        (fp32)  -> LIF1 -> s1 duplicated into A2'
//   A2' = [s1 | s1]       (K=6144)   W2' = [w2h | w2m]
//   y   = A2' @ W2'^T        (fp32)  -> LIF2 -> out
// GEMMs: 128x128 tile, BK=64, cp.async double buffer, ldmatrix + m16n8k16.
// ============================================================================

#define MT 25088      // T*B*N = 4*32*196
#define MR 6272       // B*N
#define N1 3072
#define N2 768
#define K1 2304       // 3*768
#define K2 6144       // 2*3072

__device__ __align__(128) __half g_A1[(size_t)MT * K1];
__device__ __align__(128) __half g_W1[(size_t)N1 * K1];
__device__ __align__(128) __half g_A2[(size_t)MT * K2];
__device__ __align__(128) __half g_W2[(size_t)N2 * K2];
__device__ __align__(128) float  g_h [(size_t)MT * N1];
__device__ __align__(128) float  g_y [(size_t)MT * N2];

// ---------------- helpers ----------------
__device__ __forceinline__ uint32_t smem_u32(const void* p) {
    uint32_t a;
    asm("{ .reg .u64 t; cvta.to.shared.u64 t, %1; cvt.u32.u64 %0, t; }" : "=r"(a) : "l"(p));
    return a;
}
__device__ __forceinline__ void cp_async16(uint32_t dst, const void* src) {
    asm volatile("cp.async.cg.shared.global [%0], [%1], 16;" :: "r"(dst), "l"(src) : "memory");
}
__device__ __forceinline__ void cp_commit() { asm volatile("cp.async.commit_group;" ::: "memory"); }
__device__ __forceinline__ void cp_wait1()  { asm volatile("cp.async.wait_group 1;" ::: "memory"); }
__device__ __forceinline__ void cp_wait0()  { asm volatile("cp.async.wait_group 0;" ::: "memory"); }
__device__ __forceinline__ void ldmx4(uint32_t* r, uint32_t addr) {
    asm volatile("ldmatrix.sync.aligned.m8n8.x4.shared.b16 {%0,%1,%2,%3}, [%4];"
                 : "=r"(r[0]), "=r"(r[1]), "=r"(r[2]), "=r"(r[3]) : "r"(addr));
}
__device__ __forceinline__ void mma16816(float* d, const uint32_t* a, uint32_t b0, uint32_t b1) {
    asm volatile(
        "mma.sync.aligned.m16n8k16.row.col.f32.f16.f16.f32 "
        "{%0,%1,%2,%3}, {%4,%5,%6,%7}, {%8,%9}, {%0,%1,%2,%3};"
        : "+f"(d[0]), "+f"(d[1]), "+f"(d[2]), "+f"(d[3])
        : "r"(a[0]), "r"(a[1]), "r"(a[2]), "r"(a[3]), "r"(b0), "r"(b1));
}
__device__ __forceinline__ uint32_t packh2(float a, float b) {
    __half2 h = __floats2half2_rn(a, b);
    return *(uint32_t*)&h;
}

// ---------------- GEMM: C[M,N] = A[M,K] @ B[N,K]^T (fp16 in, fp32 out) ----------------
// 128x128 tile, BK=64 (row = 128B, XOR-swizzled in 16B chunks), 256 threads,
// 8 warps as 4(m) x 2(n): warp tile 32m x 64n. Double-buffered cp.async.
__global__ __launch_bounds__(256, 2)
void hgemm_kernel(const __half* __restrict__ A, const __half* __restrict__ B,
                  float* __restrict__ C, int K, int N)
{
    extern __shared__ __align__(128) char smem_raw[];
    const uint32_t sbase = smem_u32(smem_raw);

    const int tid  = threadIdx.x;
    const int wid  = tid >> 5;
    const int lane = tid & 31;
    const int m0   = blockIdx.y * 128;
    const int n0   = blockIdx.x * 128;

    const int wm0 = (wid >> 1) * 32;     // warp m offset in tile
    const int wn0 = (wid & 1) * 64;      // warp n offset in tile

    // loader geometry: row = tid>>3 (+j*32), 16B chunk = tid&7
    const int lr = tid >> 3;
    const int lc = tid & 7;

    float acc[2][8][4];
#pragma unroll
    for (int mi = 0; mi < 2; mi++)
#pragma unroll
        for (int j = 0; j < 8; j++)
#pragma unroll
            for (int r = 0; r < 4; r++) acc[mi][j][r] = 0.0f;

    const int S = K >> 6;

#define LOAD_STAGE(sidx)                                                            \
    do {                                                                            \
        const int k0_ = (sidx) << 6;                                                \
        const uint32_t Ad = sbase + ((sidx) & 1) * 32768u;                          \
        const uint32_t Bd = Ad + 16384u;                                            \
        _Pragma("unroll")                                                           \
        for (int j = 0; j < 4; j++) {                                               \
            const int r_ = lr + j * 32;                                             \
            const uint32_t doff = (uint32_t)(r_ * 128 + ((lc ^ (r_ & 7)) << 4));    \
            cp_async16(Ad + doff,                                                   \
                       (const char*)(A + (size_t)(m0 + r_) * K + k0_) + lc * 16);   \
            cp_async16(Bd + doff,                                                   \
                       (const char*)(B + (size_t)(n0 + r_) * K + k0_) + lc * 16);   \
        }                                                                           \
    } while (0)

    LOAD_STAGE(0);
    cp_commit();

    // per-thread ldmatrix address bases
    const int g  = lane >> 3;      // address group 0..3
    const int r8 = lane & 7;
    // A fragment: reg order (m0-7,k0-7)(m8-15,k0-7)(m0-7,k8-15)(m8-15,k8-15)
    int a_m[2]; uint32_t a_rowoff[2];
#pragma unroll
    for (int mi = 0; mi < 2; mi++) {
        a_m[mi] = wm0 + mi * 16 + (g & 1) * 8 + r8;
        a_rowoff[mi] = (uint32_t)(a_m[mi] * 128);
    }
    // B fragment (non-trans ldmatrix on [N][K]): (n0-7,k0-7)(n0-7,k8-15)(n8-15,k0-7)(n8-15,k8-15)
    int b_n[4]; uint32_t b_rowoff[4];
#pragma unroll
    for (int p = 0; p < 4; p++) {
        b_n[p] = wn0 + p * 16 + (g >> 1) * 8 + r8;
        b_rowoff[p] = (uint32_t)(b_n[p] * 128);
    }

    for (int s = 0; s < S; s++) {
        if (s + 1 < S) { LOAD_STAGE(s + 1); cp_commit(); cp_wait1(); }
        else           { cp_wait0(); }
        __syncthreads();

        const uint32_t Ab = sbase + (uint32_t)((s & 1) * 32768);
        const uint32_t Bb = Ab + 16384u;

#pragma unroll
        for (int ki = 0; ki < 4; ki++) {
            uint32_t af[2][4];
#pragma unroll
            for (int mi = 0; mi < 2; mi++) {
                const int c = 2 * ki + (g >> 1);
                ldmx4(af[mi], Ab + a_rowoff[mi] + (uint32_t)(((c ^ (a_m[mi] & 7)) << 4)));
            }
            uint32_t bf[4][4];
#pragma unroll
            for (int p = 0; p < 4; p++) {
                const int c = 2 * ki + (g & 1);
                ldmx4(bf[p], Bb + b_rowoff[p] + (uint32_t)(((c ^ (b_n[p] & 7)) << 4)));
            }
#pragma unroll
            for (int mi = 0; mi < 2; mi++)
#pragma unroll
                for (int p = 0; p < 4; p++) {
                    mma16816(acc[mi][2 * p],     af[mi], bf[p][0], bf[p][1]);
                    mma16816(acc[mi][2 * p + 1], af[mi], bf[p][2], bf[p][3]);
                }
        }
        __syncthreads();
    }

    // epilogue
#pragma unroll
    for (int mi = 0; mi < 2; mi++) {
        const int row = m0 + wm0 + mi * 16 + (lane >> 2);
#pragma unroll
        for (int j = 0; j < 8; j++) {
            const int col = n0 + wn0 + j * 8 + (lane & 3) * 2;
            float* p0 = C + (size_t)row * N + col;
            *(float2*)p0 = make_float2(acc[mi][j][0], acc[mi][j][1]);
            float* p1 = p0 + (size_t)8 * N;
            *(float2*)p1 = make_float2(acc[mi][j][2], acc[mi][j][3]);
        }
    }
#undef LOAD_STAGE
}

// ---------------- split kernels ----------------
// x (fp32 [MT][768]) -> A1' fp16 [MT][2304] = [xh | xm | xh]
__global__ void split_x_kernel(const float* __restrict__ x, __half* __restrict__ A1)
{
    int i = blockIdx.x * blockDim.x + threadIdx.x;
    if (i >= MT * 192) return;
    const int row = i / 192, col = (i % 192) * 4;
    float4 v = *(const float4*)(x + (size_t)row * 768 + col);
    float a[4] = {v.x, v.y, v.z, v.w};
    float hs[4], ms[4];
#pragma unroll
    for (int k = 0; k < 4; k++) {
        __half h = __float2half_rn(a[k]);
        hs[k] = __half2float(h);
        ms[k] = a[k] - hs[k];
    }
    uint2 ph = make_uint2(packh2(hs[0], hs[1]), packh2(hs[2], hs[3]));
    uint2 pm = make_uint2(packh2(ms[0], ms[1]), packh2(ms[2], ms[3]));
    __half* d = A1 + (size_t)row * K1 + col;
    *(uint2*)d          = ph;
    *(uint2*)(d + 768)  = pm;
    *(uint2*)(d + 1536) = ph;
}

// W1 (fp32 [3072][768]) -> W1' fp16 [3072][2304] = [w1h | w1h | w1m]
__global__ void split_w1_kernel(const float* __restrict__ w, __half* __restrict__ W1p)
{
    int i = blockIdx.x * blockDim.x + threadIdx.x;
    if (i >= N1 * 192) return;
    const int row = i / 192, col = (i % 192) * 4;
    float4 v = *(const float4*)(w + (size_t)row * 768 + col);
    float a[4] = {v.x, v.y, v.z, v.w};
    float hs[4], ms[4];
#pragma unroll
    for (int k = 0; k < 4; k++) {
        __half h = __float2half_rn(a[k]);
        hs[k] = __half2float(h);
        ms[k] = a[k] - hs[k];
    }
    uint2 ph = make_uint2(packh2(hs[0], hs[1]), packh2(hs[2], hs[3]));
    uint2 pm = make_uint2(packh2(ms[0], ms[1]), packh2(ms[2], ms[3]));
    __half* d = W1p + (size_t)row * K1 + col;
    *(uint2*)d          = ph;
    *(uint2*)(d + 768)  = ph;
    *(uint2*)(d + 1536) = pm;
}

// W2 (fp32 [768][3072]) -> W2' fp16 [768][6144] = [w2h | w2m]
__global__ void split_w2_kernel(const float* __restrict__ w, __half* __restrict__ W2p)
{
    int i = blockIdx.x * blockDim.x + threadIdx.x;
    if (i >= N2 * 768) return;
    const int row = i / 768, col = (i % 768) * 4;
    float4 v = *(const float4*)(w + (size_t)row * 3072 + col);
    float a[4] = {v.x, v.y, v.z, v.w};
    float hs[4], ms[4];
#pragma unroll
    for (int k = 0; k < 4; k++) {
        __half h = __float2half_rn(a[k]);
        hs[k] = __half2float(h);
        ms[k] = a[k] - hs[k];
    }
    uint2 ph = make_uint2(packh2(hs[0], hs[1]), packh2(hs[2], hs[3]));
    uint2 pm = make_uint2(packh2(ms[0], ms[1]), packh2(ms[2], ms[3]));
    __half* d = W2p + (size_t)row * K2 + col;
    *(uint2*)d          = ph;
    *(uint2*)(d + 3072) = pm;
}

// ---------------- LIF kernels ----------------
// LIF1: h fp32 [t*MR+m][3072] -> s1 spikes fp16, written twice into A2' [t*MR+m][6144]
__global__ void lif1_kernel(const float* __restrict__ h, const float* __restrict__ b1,
                            __half* __restrict__ A2)
{
    int i = blockIdx.x * blockDim.x + threadIdx.x;
    if (i >= MR * (N1 / 4)) return;
    const int m = i / (N1 / 4), col = (i % (N1 / 4)) * 4;
    const float4 bb = *(const float4*)(b1 + col);
    float v[4] = {0.f, 0.f, 0.f, 0.f};
#pragma unroll
    for (int t = 0; t < 4; t++) {
        const size_t row = (size_t)(t * MR + m);
        float4 hv = *(const float4*)(h + row * N1 + col);
        float hh[4] = {hv.x + bb.x, hv.y + bb.y, hv.z + bb.z, hv.w + bb.w};
        float s[4];
#pragma unroll
        for (int k = 0; k < 4; k++) {
            v[k] = v[k] + (hh[k] - v[k]) * 0.5f;
            s[k] = (v[k] >= 1.0f) ? 1.0f : 0.0f;
            v[k] = v[k] * (1.0f - s[k]);
        }
        uint2 pk = make_uint2(packh2(s[0], s[1]), packh2(s[2], s[3]));
        __half* d = A2 + row * K2 + col;
        *(uint2*)d          = pk;
        *(uint2*)(d + N1)   = pk;
    }
}

// LIF2: y fp32 [t*MR+m][768] -> out fp32 (same layout)
__global__ void lif2_kernel(const float* __restrict__ y, const float* __restrict__ b2,
                            float* __restrict__ out)
{
    int i = blockIdx.x * blockDim.x + threadIdx.x;
    if (i >= MR * (N2 / 4)) return;
    const int m = i / (N2 / 4), col = (i % (N2 / 4)) * 4;
    const float4 bb = *(const float4*)(b2 + col);
    float v[4] = {0.f, 0.f, 0.f, 0.f};
#pragma unroll
    for (int t = 0; t < 4; t++) {
        const size_t row = (size_t)(t * MR + m);
        float4 yv = *(const float4*)(y + row * N2 + col);
        float hh[4] = {yv.x + bb.x, yv.y + bb.y, yv.z + bb.z, yv.w + bb.w};
        float s[4];
#pragma unroll
        for (int k = 0; k < 4; k++) {
            v[k] = v[k] + (hh[k] - v[k]) * 0.5f;
            s[k] = (v[k] >= 1.0f) ? 1.0f : 0.0f;
            v[k] = v[k] * (1.0f - s[k]);
        }
        *(float4*)(out + row * N2 + col) = make_float4(s[0], s[1], s[2], s[3]);
    }
}

// ---------------- host ----------------
extern "C" void kernel_launch(void* const* d_in, const int* in_sizes, int n_in,
                              void* d_out, int out_size)
{
    const float* x  = (const float*)d_in[0];
    const float* W1 = (const float*)d_in[1];
    const float* b1 = (const float*)d_in[2];
    const float* W2 = (const float*)d_in[3];
    const float* b2 = (const float*)d_in[4];
    float* out = (float*)d_out;

    __half *A1, *W1p, *A2, *W2p;
    float *h, *y;
    cudaGetSymbolAddress((void**)&A1,  g_A1);
    cudaGetSymbolAddress((void**)&W1p, g_W1);
    cudaGetSymbolAddress((void**)&A2,  g_A2);
    cudaGetSymbolAddress((void**)&W2p, g_W2);
    cudaGetSymbolAddress((void**)&h,   g_h);
    cudaGetSymbolAddress((void**)&y,   g_y);

    const int SMEM = 2 * 32768;   // 64KB double-buffered A+B tiles
    cudaFuncSetAttribute(hgemm_kernel, cudaFuncAttributeMaxDynamicSharedMemorySize, SMEM);

    // splits
    {
        int n = MT * 192;
        split_x_kernel<<<(n + 255) / 256, 256>>>(x, A1);
    }
    {
        int n = N1 * 192;
        split_w1_kernel<<<(n + 255) / 256, 256>>>(W1, W1p);
    }
    {
        int n = N2 * 768;
        split_w2_kernel<<<(n + 255) / 256, 256>>>(W2, W2p);
    }

    // GEMM1: h = A1' @ W1'^T   (M=25088, N=3072, K=2304)
    {
        dim3 grid(N1 / 128, MT / 128);   // (24, 196)
        hgemm_kernel<<<grid, 256, SMEM>>>(A1, W1p, h, K1, N1);
    }
    // LIF1 -> A2'
    {
        int n = MR * (N1 / 4);
        lif1_kernel<<<(n + 255) / 256, 256>>>(h, b1, A2);
    }
    // GEMM2: y = A2' @ W2'^T   (M=25088, N=768, K=6144)
    {
        dim3 grid(N2 / 128, MT / 128);   // (6, 196)
        hgemm_kernel<<<grid, 256, SMEM>>>(A2, W2p, y, K2, N2);
    }
    // LIF2 -> out
    {
        int n = MR * (N2 / 4);
        lif2_kernel<<<(n + 255) / 256, 256>>>(y, b2, out);
    }
}